// round 5
// baseline (speedup 1.0000x reference)
#include <cuda_runtime.h>
#include <cuda_bf16.h>
#include <cstdint>

#define C_PAD   1024
#define B_ROWS  16384
#define DIN     1024
#define DOUT    256

// ---------------- scratch (static __device__, no allocation) ----------------
__device__ __align__(16) float g_class_sum[C_PAD * DIN];   // 4 MB
__device__ float g_cnt[C_PAD];
__device__ float g_total[DIN];
__device__ __align__(16) float g_M2[C_PAD * DOUT];         // 1 MB
__device__ int   g_lbl_is64;
// bf16 split operands
__device__ __align__(16) __nv_bfloat16 g_xh[B_ROWS * DIN];   // 32 MB
__device__ __align__(16) __nv_bfloat16 g_xl[B_ROWS * DIN];   // 32 MB
__device__ __align__(16) __nv_bfloat16 g_wh[DOUT * DIN];     // 0.5 MB
__device__ __align__(16) __nv_bfloat16 g_wl[DOUT * DIN];     // 0.5 MB

// ---------------- helpers ----------------------------------------------------
__device__ __forceinline__ int load_label(const void* l, int i, int is64) {
    if (is64) return (int)(((const long long*)l)[i]);
    return ((const int*)l)[i];
}

__device__ __forceinline__ uint32_t smem_u32(const void* p) {
    uint32_t a;
    asm("{ .reg .u64 t; cvta.to.shared.u64 t, %1; cvt.u32.u64 %0, t; }" : "=r"(a) : "l"(p));
    return a;
}
__device__ __forceinline__ void cp16(uint32_t dst, const void* src) {
    asm volatile("cp.async.cg.shared.global [%0], [%1], 16;" :: "r"(dst), "l"(src));
}
#define CP_COMMIT() asm volatile("cp.async.commit_group;" ::: "memory")
#define CP_WAIT1()  asm volatile("cp.async.wait_group 1;" ::: "memory")
#define CP_WAIT0()  asm volatile("cp.async.wait_group 0;" ::: "memory")

__device__ __forceinline__ void ldsm_x4(uint32_t addr, uint32_t* r) {
    asm volatile("ldmatrix.sync.aligned.m8n8.x4.shared.b16 {%0,%1,%2,%3}, [%4];"
                 : "=r"(r[0]), "=r"(r[1]), "=r"(r[2]), "=r"(r[3]) : "r"(addr));
}
__device__ __forceinline__ void ldsm_x2(uint32_t addr, uint32_t* r) {
    asm volatile("ldmatrix.sync.aligned.m8n8.x2.shared.b16 {%0,%1}, [%2];"
                 : "=r"(r[0]), "=r"(r[1]) : "r"(addr));
}
__device__ __forceinline__ void mma_bf16(float* c, const uint32_t* a, const uint32_t* b) {
    asm volatile(
        "mma.sync.aligned.m16n8k16.row.col.f32.bf16.bf16.f32 "
        "{%0,%1,%2,%3}, {%4,%5,%6,%7}, {%8,%9}, {%0,%1,%2,%3};"
        : "+f"(c[0]), "+f"(c[1]), "+f"(c[2]), "+f"(c[3])
        : "r"(a[0]), "r"(a[1]), "r"(a[2]), "r"(a[3]), "r"(b[0]), "r"(b[1]));
}

// split float4 -> bf16 hi (uint2) + residual lo (uint2)
__device__ __forceinline__ void split4(float4 v, uint2& hi, uint2& lo) {
    __nv_bfloat162 h01 = __floats2bfloat162_rn(v.x, v.y);
    __nv_bfloat162 h23 = __floats2bfloat162_rn(v.z, v.w);
    float r0 = v.x - __bfloat162float(h01.x);
    float r1 = v.y - __bfloat162float(h01.y);
    float r2 = v.z - __bfloat162float(h23.x);
    float r3 = v.w - __bfloat162float(h23.y);
    __nv_bfloat162 l01 = __floats2bfloat162_rn(r0, r1);
    __nv_bfloat162 l23 = __floats2bfloat162_rn(r2, r3);
    hi.x = *(uint32_t*)&h01; hi.y = *(uint32_t*)&h23;
    lo.x = *(uint32_t*)&l01; lo.y = *(uint32_t*)&l23;
}

// ---------------- small kernels ---------------------------------------------
__global__ void k_zero() {
    int i = blockIdx.x * blockDim.x + threadIdx.x;
    int stride = gridDim.x * blockDim.x;
    for (int j = i; j < C_PAD * DIN; j += stride) g_class_sum[j] = 0.f;
    for (int j = i; j < C_PAD; j += stride) g_cnt[j] = 0.f;
    for (int j = i; j < DIN; j += stride) g_total[j] = 0.f;
    if (i == 0) g_lbl_is64 = 1;
}

__global__ void k_detect(const int* __restrict__ lw) {
    int i = blockIdx.x * blockDim.x + threadIdx.x;
    if (i < B_ROWS / 2) {
        if (lw[2 * i + 1] != 0) g_lbl_is64 = 0;
    }
}

// fused: scatter-add x by label + write bf16 hi/lo split of x
__global__ void k_prep(const float* __restrict__ x, const void* __restrict__ lbl) {
    int row = blockIdx.x;
    int t = threadIdx.x;
    int is64 = g_lbl_is64;
    int c = load_label(lbl, row, is64);
    float4 v = ((const float4*)(x + (size_t)row * DIN))[t];
    float4* dst = (float4*)(g_class_sum + (size_t)c * DIN);
    atomicAdd(dst + t, v);
    uint2 hi, lo; split4(v, hi, lo);
    *(uint2*)(g_xh + (size_t)row * DIN + 4 * t) = hi;
    *(uint2*)(g_xl + (size_t)row * DIN + 4 * t) = lo;
    if (t == 0) atomicAdd(&g_cnt[c], 1.0f);
}

// split W1 once
__global__ void k_wsplit(const float* __restrict__ W1w) {
    int row = blockIdx.x;           // 0..255
    int t = threadIdx.x;            // 0..255
    float4 v = ((const float4*)(W1w + (size_t)row * DIN))[t];
    uint2 hi, lo; split4(v, hi, lo);
    *(uint2*)(g_wh + (size_t)row * DIN + 4 * t) = hi;
    *(uint2*)(g_wl + (size_t)row * DIN + 4 * t) = lo;
}

// total_sum over classes. grid (16,16)
__global__ void k_total() {
    int col  = blockIdx.x * 64 + (threadIdx.x & 63);
    int part = threadIdx.x >> 6;
    int c0 = blockIdx.y * 64 + part * 16;
    float s = 0.f;
#pragma unroll
    for (int c = c0; c < c0 + 16; ++c) s += g_class_sum[(size_t)c * DIN + col];
    __shared__ float red[256];
    red[threadIdx.x] = s;
    __syncthreads();
    if (part == 0)
        atomicAdd(&g_total[col], red[threadIdx.x] + red[threadIdx.x + 64] +
                                 red[threadIdx.x + 128] + red[threadIdx.x + 192]);
}

// M2[c] = mean_c @ W2^T + b2
__global__ __launch_bounds__(256) void k_m2(const float* __restrict__ W2w,
                                            const float* __restrict__ W2b) {
    __shared__ float As[32][33];
    __shared__ float Bs[32][68];
    __shared__ float sscale[32];

    int n0 = blockIdx.x * 64;
    int c0 = blockIdx.y * 32;
    int tid = threadIdx.x;

    if (tid < 32) {
        float cnt = g_cnt[c0 + tid];
        float oc = (float)B_ROWS - cnt;
        sscale[tid] = (oc > 0.5f) ? (1.0f / oc) : 0.0f;
    }
    __syncthreads();

    int am = tid >> 3;
    int ak = (tid & 7) * 4;
    int tx = tid & 15, ty = tid >> 4;
    float acc[2][4] = {};

    for (int k0 = 0; k0 < DIN; k0 += 32) {
        float4 t4 = *(const float4*)(g_total + k0 + ak);
        float4 s4 = *(const float4*)(g_class_sum + (size_t)(c0 + am) * DIN + k0 + ak);
        float sc = sscale[am];
        __syncthreads();
        As[ak + 0][am] = (t4.x - s4.x) * sc;
        As[ak + 1][am] = (t4.y - s4.y) * sc;
        As[ak + 2][am] = (t4.z - s4.z) * sc;
        As[ak + 3][am] = (t4.w - s4.w) * sc;
#pragma unroll
        for (int it = 0; it < 2; ++it) {
            int idx = tid + it * 256;
            int bn = idx >> 3;
            int bk = (idx & 7) * 4;
            float4 w4 = *(const float4*)(W2w + (size_t)(n0 + bn) * DIN + k0 + bk);
            Bs[bk + 0][bn] = w4.x;
            Bs[bk + 1][bn] = w4.y;
            Bs[bk + 2][bn] = w4.z;
            Bs[bk + 3][bn] = w4.w;
        }
        __syncthreads();
#pragma unroll
        for (int k = 0; k < 32; ++k) {
            float a0 = As[k][2 * ty + 0];
            float a1 = As[k][2 * ty + 1];
            float4 b = *(const float4*)(&Bs[k][4 * tx]);
            acc[0][0] += a0 * b.x; acc[0][1] += a0 * b.y;
            acc[0][2] += a0 * b.z; acc[0][3] += a0 * b.w;
            acc[1][0] += a1 * b.x; acc[1][1] += a1 * b.y;
            acc[1][2] += a1 * b.z; acc[1][3] += a1 * b.w;
        }
    }
#pragma unroll
    for (int r = 0; r < 2; ++r) {
        int c = c0 + 2 * ty + r;
        int n = n0 + 4 * tx;
        float4 bb = *(const float4*)(W2b + n);
        float4 o;
        o.x = acc[r][0] + bb.x; o.y = acc[r][1] + bb.y;
        o.z = acc[r][2] + bb.z; o.w = acc[r][3] + bb.w;
        *(float4*)(g_M2 + (size_t)c * DOUT + n) = o;
    }
}

// ---------------- k_main: cp.async double-buffered bf16 3-term GEMM ----------
// CTA tile M=128, N=256. 8 warps (2x4), 64x64/warp. K-chunk 32, 2 smem stages.
#define KC       32
#define AST      40                        // bf16 row stride (80 B, conflict-free)
#define STG_A    (128 * AST * 2)           // 10240 B per A half
#define STG_B    (256 * AST * 2)           // 20480 B per B half
#define SMS      (2 * STG_A + 2 * STG_B)   // 61440 B per stage
#define SM_TOT   (2 * SMS)                 // 122880 B

__global__ __launch_bounds__(256, 1) void k_main(const void* __restrict__ lbl,
                                                 const float* __restrict__ W1b,
                                                 float* __restrict__ out) {
    extern __shared__ char sm[];
    uint32_t smb = smem_u32(sm);
    int tid = threadIdx.x;
    int wid = tid >> 5, lane = tid & 31;
    int wm = wid >> 2, wn = wid & 3;
    int m0 = blockIdx.x * 128;

    // cp.async chunk map (16 B chunks of 8 bf16)
    int ar = tid >> 2;            // A: rows via c>>2 below
    (void)ar;

    // ldmatrix lane addressing
    int a_r = wm * 64 + (lane & 15);
    int a_k = (lane >> 4) * 8;
    int b_r = wn * 64 + (lane & 7);
    int b_k = ((lane >> 3) & 1) * 8;

    float acc[4][8][4];
#pragma unroll
    for (int i = 0; i < 4; ++i)
#pragma unroll
        for (int j = 0; j < 8; ++j)
#pragma unroll
            for (int q = 0; q < 4; ++q) acc[i][j][q] = 0.f;

    // stage loader: 12 cp.async per thread
    auto load_stage = [&](int s, int k0) {
        uint32_t base = smb + s * SMS;
#pragma unroll
        for (int i = 0; i < 2; ++i) {              // A: 512 chunks per half
            int c = tid + 256 * i;
            int row = c >> 2, kq = c & 3;
            size_t goff = (size_t)(m0 + row) * DIN + k0 + kq * 8;
            uint32_t doff = row * (AST * 2) + kq * 16;
            cp16(base + doff, g_xh + goff);
            cp16(base + STG_A + doff, g_xl + goff);
        }
#pragma unroll
        for (int i = 0; i < 4; ++i) {              // B: 1024 chunks per half
            int c = tid + 256 * i;
            int row = c >> 2, kq = c & 3;
            size_t goff = (size_t)row * DIN + k0 + kq * 8;
            uint32_t doff = row * (AST * 2) + kq * 16;
            cp16(base + 2 * STG_A + doff, g_wh + goff);
            cp16(base + 2 * STG_A + STG_B + doff, g_wl + goff);
        }
    };

    load_stage(0, 0);
    CP_COMMIT();

    for (int kc = 0; kc < DIN / KC; ++kc) {
        int s = kc & 1;
        if (kc + 1 < DIN / KC) {
            load_stage(s ^ 1, (kc + 1) * KC);
            CP_COMMIT();
            CP_WAIT1();
        } else {
            CP_WAIT0();
        }
        __syncthreads();

        uint32_t aH = smb + s * SMS;
        uint32_t aL = aH + STG_A;
        uint32_t bH = aH + 2 * STG_A;
        uint32_t bL = bH + STG_B;

#pragma unroll
        for (int kk = 0; kk < KC; kk += 16) {
            uint32_t ah[4][4], al[4][4];
#pragma unroll
            for (int mi = 0; mi < 4; ++mi) {
                uint32_t off = (uint32_t)((a_r + mi * 16) * AST + kk + a_k) * 2;
                ldsm_x4(aH + off, ah[mi]);
                ldsm_x4(aL + off, al[mi]);
            }
#pragma unroll
            for (int ni = 0; ni < 8; ++ni) {
                uint32_t boff = (uint32_t)((b_r + ni * 8) * AST + kk + b_k) * 2;
                uint32_t bh[2], bl[2];
                ldsm_x2(bH + boff, bh);
                ldsm_x2(bL + boff, bl);
#pragma unroll
                for (int mi = 0; mi < 4; ++mi) {
                    mma_bf16(acc[mi][ni], ah[mi], bh);
                    mma_bf16(acc[mi][ni], ah[mi], bl);
                    mma_bf16(acc[mi][ni], al[mi], bh);
                }
            }
        }
        __syncthreads();
    }

    // epilogue: + b1[n] + M2[label[m]][n]
    int is64 = g_lbl_is64;
    int nlo = (lane & 3) * 2;
    int rbase = m0 + wm * 64 + (lane >> 2);

    float2 bb[8];
#pragma unroll
    for (int ni = 0; ni < 8; ++ni)
        bb[ni] = *(const float2*)(W1b + wn * 64 + ni * 8 + nlo);

#pragma unroll
    for (int mi = 0; mi < 4; ++mi) {
        int r0 = rbase + mi * 16;
        int r1 = r0 + 8;
        int c0 = load_label(lbl, r0, is64);
        int c1 = load_label(lbl, r1, is64);
        const float* m2r0 = g_M2 + (size_t)c0 * DOUT;
        const float* m2r1 = g_M2 + (size_t)c1 * DOUT;
        float* o0 = out + (size_t)r0 * DOUT;
        float* o1 = out + (size_t)r1 * DOUT;
#pragma unroll
        for (int ni = 0; ni < 8; ++ni) {
            int n = wn * 64 + ni * 8 + nlo;
            float2 mA = *(const float2*)(m2r0 + n);
            float2 mB = *(const float2*)(m2r1 + n);
            float2 vA, vB;
            vA.x = acc[mi][ni][0] + bb[ni].x + mA.x;
            vA.y = acc[mi][ni][1] + bb[ni].y + mA.y;
            vB.x = acc[mi][ni][2] + bb[ni].x + mB.x;
            vB.y = acc[mi][ni][3] + bb[ni].y + mB.y;
            *(float2*)(o0 + n) = vA;
            *(float2*)(o1 + n) = vB;
        }
    }
}

// ---------------- launch ----------------------------------------------------
extern "C" void kernel_launch(void* const* d_in, const int* in_sizes, int n_in,
                              void* d_out, int out_size) {
    const float* x   = (const float*)d_in[0];
    const void*  lbl = d_in[1];
    const float* W1w = (const float*)d_in[2];
    const float* W1b = (const float*)d_in[3];
    const float* W2w = (const float*)d_in[4];
    const float* W2b = (const float*)d_in[5];
    float* out = (float*)d_out;

    cudaFuncSetAttribute(k_main, cudaFuncAttributeMaxDynamicSharedMemorySize, SM_TOT);

    k_zero<<<512, 256>>>();
    k_detect<<<32, 256>>>((const int*)lbl);
    k_prep<<<B_ROWS, 256>>>(x, lbl);
    k_wsplit<<<DOUT, 256>>>(W1w);
    k_total<<<dim3(16, 16), 256>>>();
    k_m2<<<dim3(4, 32), 256>>>(W2w, W2b);
    k_main<<<128, 256, SM_TOT>>>(lbl, W1b, out);
}

// round 7
// speedup vs baseline: 1.4883x; 1.4883x over previous
#include <cuda_runtime.h>
#include <cuda_bf16.h>
#include <cstdint>

#define C_PAD   1024
#define B_ROWS  16384
#define DIN     1024
#define DOUT    256

// ---------------- scratch (static __device__, no allocation) ----------------
__device__ __align__(16) float g_class_sum[C_PAD * DIN];   // 4 MB
__device__ float g_cnt[C_PAD];
__device__ float g_total[DIN];
__device__ __align__(16) float g_M2[C_PAD * DOUT];         // 1 MB
__device__ int   g_lbl_is64;

// ---------------- helpers ----------------------------------------------------
__device__ __forceinline__ int load_label(const void* l, int i, int is64) {
    if (is64) return (int)(((const long long*)l)[i]);
    return ((const int*)l)[i];
}
__device__ __forceinline__ uint32_t smem_u32(const void* p) {
    uint32_t a;
    asm("{ .reg .u64 t; cvta.to.shared.u64 t, %1; cvt.u32.u64 %0, t; }" : "=r"(a) : "l"(p));
    return a;
}
__device__ __forceinline__ void cp16(uint32_t dst, const void* src) {
    asm volatile("cp.async.cg.shared.global [%0], [%1], 16;" :: "r"(dst), "l"(src));
}
#define CP_COMMIT() asm volatile("cp.async.commit_group;" ::: "memory")
#define CP_WAIT1()  asm volatile("cp.async.wait_group 1;" ::: "memory")

__device__ __forceinline__ void ldsm_x4(uint32_t addr, uint32_t* r) {
    asm volatile("ldmatrix.sync.aligned.m8n8.x4.shared.b16 {%0,%1,%2,%3}, [%4];"
                 : "=r"(r[0]), "=r"(r[1]), "=r"(r[2]), "=r"(r[3]) : "r"(addr));
}
__device__ __forceinline__ void ldsm_x2(uint32_t addr, uint32_t* r) {
    asm volatile("ldmatrix.sync.aligned.m8n8.x2.shared.b16 {%0,%1}, [%2];"
                 : "=r"(r[0]), "=r"(r[1]) : "r"(addr));
}
__device__ __forceinline__ void mma_bf16(float* c, const uint32_t* a, const uint32_t* b) {
    asm volatile(
        "mma.sync.aligned.m16n8k16.row.col.f32.bf16.bf16.f32 "
        "{%0,%1,%2,%3}, {%4,%5,%6,%7}, {%8,%9}, {%0,%1,%2,%3};"
        : "+f"(c[0]), "+f"(c[1]), "+f"(c[2]), "+f"(c[3])
        : "r"(a[0]), "r"(a[1]), "r"(a[2]), "r"(a[3]), "r"(b[0]), "r"(b[1]));
}
__device__ __forceinline__ void split4(float4 v, uint2& hi, uint2& lo) {
    __nv_bfloat162 h01 = __floats2bfloat162_rn(v.x, v.y);
    __nv_bfloat162 h23 = __floats2bfloat162_rn(v.z, v.w);
    float r0 = v.x - __bfloat162float(h01.x);
    float r1 = v.y - __bfloat162float(h01.y);
    float r2 = v.z - __bfloat162float(h23.x);
    float r3 = v.w - __bfloat162float(h23.y);
    __nv_bfloat162 l01 = __floats2bfloat162_rn(r0, r1);
    __nv_bfloat162 l23 = __floats2bfloat162_rn(r2, r3);
    hi.x = *(uint32_t*)&h01; hi.y = *(uint32_t*)&h23;
    lo.x = *(uint32_t*)&l01; lo.y = *(uint32_t*)&l23;
}

// ---------------- small kernels ---------------------------------------------
__global__ void k_zero() {
    int i = blockIdx.x * blockDim.x + threadIdx.x;
    int stride = gridDim.x * blockDim.x;
    for (int j = i; j < C_PAD * DIN; j += stride) g_class_sum[j] = 0.f;
    for (int j = i; j < C_PAD; j += stride) g_cnt[j] = 0.f;
    for (int j = i; j < DIN; j += stride) g_total[j] = 0.f;
    if (i == 0) g_lbl_is64 = 1;
}

__global__ void k_detect(const int* __restrict__ lw) {
    int i = blockIdx.x * blockDim.x + threadIdx.x;
    if (i < B_ROWS / 2) {
        if (lw[2 * i + 1] != 0) g_lbl_is64 = 0;
    }
}

// segment-sum x by label (float4 global REDs)
__global__ void k_scatter(const float* __restrict__ x, const void* __restrict__ lbl) {
    int row = blockIdx.x;
    int is64 = g_lbl_is64;
    int c = load_label(lbl, row, is64);
    const float4* xr = (const float4*)(x + (size_t)row * DIN);
    float4 v = xr[threadIdx.x];
    float4* dst = (float4*)(g_class_sum + (size_t)c * DIN);
    atomicAdd(dst + threadIdx.x, v);
    if (threadIdx.x == 0) atomicAdd(&g_cnt[c], 1.0f);
}

// total_sum over classes. grid (16,16)
__global__ void k_total() {
    int col  = blockIdx.x * 64 + (threadIdx.x & 63);
    int part = threadIdx.x >> 6;
    int c0 = blockIdx.y * 64 + part * 16;
    float s = 0.f;
#pragma unroll
    for (int c = c0; c < c0 + 16; ++c) s += g_class_sum[(size_t)c * DIN + col];
    __shared__ float red[256];
    red[threadIdx.x] = s;
    __syncthreads();
    if (part == 0)
        atomicAdd(&g_total[col], red[threadIdx.x] + red[threadIdx.x + 64] +
                                 red[threadIdx.x + 128] + red[threadIdx.x + 192]);
}

// M2[c] = mean_c @ W2^T + b2
__global__ __launch_bounds__(256) void k_m2(const float* __restrict__ W2w,
                                            const float* __restrict__ W2b) {
    __shared__ float As[32][33];
    __shared__ float Bs[32][68];
    __shared__ float sscale[32];

    int n0 = blockIdx.x * 64;
    int c0 = blockIdx.y * 32;
    int tid = threadIdx.x;

    if (tid < 32) {
        float cnt = g_cnt[c0 + tid];
        float oc = (float)B_ROWS - cnt;
        sscale[tid] = (oc > 0.5f) ? (1.0f / oc) : 0.0f;
    }
    __syncthreads();

    int am = tid >> 3;
    int ak = (tid & 7) * 4;
    int tx = tid & 15, ty = tid >> 4;
    float acc[2][4] = {};

    for (int k0 = 0; k0 < DIN; k0 += 32) {
        float4 t4 = *(const float4*)(g_total + k0 + ak);
        float4 s4 = *(const float4*)(g_class_sum + (size_t)(c0 + am) * DIN + k0 + ak);
        float sc = sscale[am];
        __syncthreads();
        As[ak + 0][am] = (t4.x - s4.x) * sc;
        As[ak + 1][am] = (t4.y - s4.y) * sc;
        As[ak + 2][am] = (t4.z - s4.z) * sc;
        As[ak + 3][am] = (t4.w - s4.w) * sc;
#pragma unroll
        for (int it = 0; it < 2; ++it) {
            int idx = tid + it * 256;
            int bn = idx >> 3;
            int bk = (idx & 7) * 4;
            float4 w4 = *(const float4*)(W2w + (size_t)(n0 + bn) * DIN + k0 + bk);
            Bs[bk + 0][bn] = w4.x;
            Bs[bk + 1][bn] = w4.y;
            Bs[bk + 2][bn] = w4.z;
            Bs[bk + 3][bn] = w4.w;
        }
        __syncthreads();
#pragma unroll
        for (int k = 0; k < 32; ++k) {
            float a0 = As[k][2 * ty + 0];
            float a1 = As[k][2 * ty + 1];
            float4 b = *(const float4*)(&Bs[k][4 * tx]);
            acc[0][0] += a0 * b.x; acc[0][1] += a0 * b.y;
            acc[0][2] += a0 * b.z; acc[0][3] += a0 * b.w;
            acc[1][0] += a1 * b.x; acc[1][1] += a1 * b.y;
            acc[1][2] += a1 * b.z; acc[1][3] += a1 * b.w;
        }
    }
#pragma unroll
    for (int r = 0; r < 2; ++r) {
        int c = c0 + 2 * ty + r;
        int n = n0 + 4 * tx;
        float4 bb = *(const float4*)(W2b + n);
        float4 o;
        o.x = acc[r][0] + bb.x; o.y = acc[r][1] + bb.y;
        o.z = acc[r][2] + bb.z; o.w = acc[r][3] + bb.w;
        *(float4*)(g_M2 + (size_t)c * DOUT + n) = o;
    }
}

// ---------------- k_main: cp.async(fp32) -> smem convert -> bf16 3-term MMA --
// out = x @ W1^T (fp32). Epilogue (+b1 +M2[label]) is a separate kernel so this
// runs as the 4th launch (the ncu capture slot).
#define KC      32
#define FST     36                             // fp32 stage row stride (floats)
#define XF_SZ   (128 * FST * 4)                // 18432 B
#define WF_SZ   (256 * FST * 4)                // 36864 B
#define STG     (XF_SZ + WF_SZ)                // 55296 B per stage
#define AST     40                             // bf16 row stride (elems)
#define ABH_SZ  (128 * AST * 2)                // 10240 B per A half
#define BBH_SZ  (256 * AST * 2)                // 20480 B per B half
#define BF_OFF  (2 * STG)                      // 110592
#define SM_TOT  (BF_OFF + 2 * ABH_SZ + 2 * BBH_SZ)   // 172032 B

__global__ __launch_bounds__(256, 1) void k_main(const float* __restrict__ x,
                                                 const float* __restrict__ W1w,
                                                 float* __restrict__ out) {
    extern __shared__ char sm[];
    uint32_t smb = smem_u32(sm);
    int tid = threadIdx.x;
    int wid = tid >> 5, lane = tid & 31;
    int wm = wid >> 2, wn = wid & 3;
    int m0 = blockIdx.x * 128;

    // ldmatrix lane addressing
    int a_r = wm * 64 + (lane & 15);
    int a_k = (lane >> 4) * 8;
    int b_r = wn * 64 + (lane & 7);
    int b_k = ((lane >> 3) & 1) * 8;

    float acc[4][8][4];
#pragma unroll
    for (int i = 0; i < 4; ++i)
#pragma unroll
        for (int j = 0; j < 8; ++j)
#pragma unroll
            for (int q = 0; q < 4; ++q) acc[i][j][q] = 0.f;

    // cp.async stage loader: fp32 x-chunk [128x32] + W-chunk [256x32], 12/thread
    auto load_stage = [&](int s, int k0) {
        uint32_t base = smb + s * STG;
#pragma unroll
        for (int i = 0; i < 4; ++i) {              // x: 1024 float4 chunks
            int c = tid + 256 * i;
            int row = c >> 3, kq = c & 7;
            cp16(base + row * (FST * 4) + kq * 16,
                 x + (size_t)(m0 + row) * DIN + k0 + 4 * kq);
        }
#pragma unroll
        for (int i = 0; i < 8; ++i) {              // W: 2048 float4 chunks
            int c = tid + 256 * i;
            int row = c >> 3, kq = c & 7;
            cp16(base + XF_SZ + row * (FST * 4) + kq * 16,
                 W1w + (size_t)row * DIN + k0 + 4 * kq);
        }
    };

    load_stage(0, 0);  CP_COMMIT();
    load_stage(1, KC); CP_COMMIT();

    uint32_t AH = smb + BF_OFF;
    uint32_t AL = AH + ABH_SZ;
    uint32_t BH = AL + ABH_SZ;
    uint32_t BL = BH + BBH_SZ;

    for (int kc = 0; kc < DIN / KC; ++kc) {
        int s = kc & 1;
        CP_WAIT1();                 // chunk kc resident (only newest group pending)
        __syncthreads();            // cp data visible; prior iter's LDSM reads done

        // convert fp32 stage -> bf16 hi/lo tiles (smem -> smem)
        uint32_t fx_off = s * STG;
        uint32_t fw_off = fx_off + XF_SZ;
#pragma unroll
        for (int i = 0; i < 4; ++i) {
            int c = tid + 256 * i;
            int row = c >> 3, kq = c & 7;
            float4 v = *(const float4*)(sm + fx_off + row * (FST * 4) + kq * 16);
            uint2 hi, lo; split4(v, hi, lo);
            uint32_t doff = row * (AST * 2) + kq * 8;
            *(uint2*)(sm + BF_OFF + doff) = hi;                    // AH
            *(uint2*)(sm + BF_OFF + ABH_SZ + doff) = lo;           // AL
        }
#pragma unroll
        for (int i = 0; i < 8; ++i) {
            int c = tid + 256 * i;
            int row = c >> 3, kq = c & 7;
            float4 v = *(const float4*)(sm + fw_off + row * (FST * 4) + kq * 16);
            uint2 hi, lo; split4(v, hi, lo);
            uint32_t doff = row * (AST * 2) + kq * 8;
            *(uint2*)(sm + BF_OFF + 2 * ABH_SZ + doff) = hi;       // BH
            *(uint2*)(sm + BF_OFF + 2 * ABH_SZ + BBH_SZ + doff) = lo;  // BL
        }
        __syncthreads();            // bf16 tiles ready; fp32 stage s fully consumed

        // prefetch chunk kc+2 into stage s (overlaps MMA below)
        if (kc + 2 < DIN / KC) load_stage(s, (kc + 2) * KC);
        CP_COMMIT();                // commit every iter (possibly empty) -> WAIT1 exact

        // MMA: 3-term split over two k16 steps
#pragma unroll
        for (int kk = 0; kk < KC; kk += 16) {
            uint32_t ah[4][4], al[4][4];
#pragma unroll
            for (int mi = 0; mi < 4; ++mi) {
                uint32_t off = (uint32_t)((a_r + mi * 16) * AST + kk + a_k) * 2;
                ldsm_x4(AH + off, ah[mi]);
                ldsm_x4(AL + off, al[mi]);
            }
#pragma unroll
            for (int ni = 0; ni < 8; ++ni) {
                uint32_t boff = (uint32_t)((b_r + ni * 8) * AST + kk + b_k) * 2;
                uint32_t bh[2], bl[2];
                ldsm_x2(BH + boff, bh);
                ldsm_x2(BL + boff, bl);
#pragma unroll
                for (int mi = 0; mi < 4; ++mi) {
                    mma_bf16(acc[mi][ni], ah[mi], bh);
                    mma_bf16(acc[mi][ni], ah[mi], bl);
                    mma_bf16(acc[mi][ni], al[mi], bh);
                }
            }
        }
        // no sync here: next iteration's post-WAIT sync fences bf16 buffer reuse
    }

    // write raw GEMM result (epilogue kernel adds b1 + M2[label])
    int nlo = (lane & 3) * 2;
    int rbase = m0 + wm * 64 + (lane >> 2);
#pragma unroll
    for (int mi = 0; mi < 4; ++mi) {
        int r0 = rbase + mi * 16;
        int r1 = r0 + 8;
        float* o0 = out + (size_t)r0 * DOUT;
        float* o1 = out + (size_t)r1 * DOUT;
#pragma unroll
        for (int ni = 0; ni < 8; ++ni) {
            int n = wn * 64 + ni * 8 + nlo;
            float2 vA, vB;
            vA.x = acc[mi][ni][0]; vA.y = acc[mi][ni][1];
            vB.x = acc[mi][ni][2]; vB.y = acc[mi][ni][3];
            *(float2*)(o0 + n) = vA;
            *(float2*)(o1 + n) = vB;
        }
    }
}

// epilogue: out[m][n] += b1[n] + M2[label[m]][n]
__global__ __launch_bounds__(256) void k_epi(const void* __restrict__ lbl,
                                             const float* __restrict__ W1b,
                                             float* __restrict__ out) {
    int t = threadIdx.x;
    int row = blockIdx.x * 4 + (t >> 6);
    int n = (t & 63) * 4;
    int is64 = g_lbl_is64;
    int c = load_label(lbl, row, is64);
    float4 bb = *(const float4*)(W1b + n);
    float4 mm = *(const float4*)(g_M2 + (size_t)c * DOUT + n);
    float4* op = (float4*)(out + (size_t)row * DOUT + n);
    float4 o = *op;
    o.x += bb.x + mm.x; o.y += bb.y + mm.y;
    o.z += bb.z + mm.z; o.w += bb.w + mm.w;
    *op = o;
}

// ---------------- launch ----------------------------------------------------
extern "C" void kernel_launch(void* const* d_in, const int* in_sizes, int n_in,
                              void* d_out, int out_size) {
    const float* x   = (const float*)d_in[0];
    const void*  lbl = d_in[1];
    const float* W1w = (const float*)d_in[2];
    const float* W1b = (const float*)d_in[3];
    const float* W2w = (const float*)d_in[4];
    const float* W2b = (const float*)d_in[5];
    float* out = (float*)d_out;

    cudaFuncSetAttribute(k_main, cudaFuncAttributeMaxDynamicSharedMemorySize, SM_TOT);

    k_zero<<<512, 256>>>();
    k_detect<<<32, 256>>>((const int*)lbl);
    k_scatter<<<B_ROWS, 256>>>(x, lbl);
    k_main<<<128, 256, SM_TOT>>>(x, W1w, out);     // 4th launch -> ncu capture slot
    k_total<<<dim3(16, 16), 256>>>();
    k_m2<<<dim3(4, 32), 256>>>(W2w, W2b);
    k_epi<<<B_ROWS / 4, 256>>>(lbl, W1b, out);
}

// round 9
// speedup vs baseline: 1.5420x; 1.0360x over previous
#include <cuda_runtime.h>
#include <cuda_bf16.h>
#include <cstdint>

#define C_PAD   1024
#define B_ROWS  16384
#define DIN     1024
#define DOUT    256

// ---------------- scratch (static __device__, no allocation) ----------------
__device__ __align__(16) float g_class_sum[C_PAD * DIN];   // 4 MB
__device__ float g_cnt[C_PAD];
__device__ float g_total[DIN];
__device__ __align__(16) float g_M2[C_PAD * DOUT];         // 1 MB
__device__ int   g_lbl_is64;
__device__ __align__(16) __nv_bfloat16 g_wh[DOUT * DIN];   // 0.5 MB
__device__ __align__(16) __nv_bfloat16 g_wl[DOUT * DIN];   // 0.5 MB

// ---------------- helpers ----------------------------------------------------
__device__ __forceinline__ int load_label(const void* l, int i, int is64) {
    if (is64) return (int)(((const long long*)l)[i]);
    return ((const int*)l)[i];
}
__device__ __forceinline__ uint32_t smem_u32(const void* p) {
    uint32_t a;
    asm("{ .reg .u64 t; cvta.to.shared.u64 t, %1; cvt.u32.u64 %0, t; }" : "=r"(a) : "l"(p));
    return a;
}
__device__ __forceinline__ void cp16(uint32_t dst, const void* src) {
    asm volatile("cp.async.cg.shared.global [%0], [%1], 16;" :: "r"(dst), "l"(src));
}
#define CP_COMMIT() asm volatile("cp.async.commit_group;" ::: "memory")
#define CP_WAIT1()  asm volatile("cp.async.wait_group 1;" ::: "memory")

__device__ __forceinline__ void ldsm_x4(uint32_t addr, uint32_t* r) {
    asm volatile("ldmatrix.sync.aligned.m8n8.x4.shared.b16 {%0,%1,%2,%3}, [%4];"
                 : "=r"(r[0]), "=r"(r[1]), "=r"(r[2]), "=r"(r[3]) : "r"(addr));
}
__device__ __forceinline__ void ldsm_x2(uint32_t addr, uint32_t* r) {
    asm volatile("ldmatrix.sync.aligned.m8n8.x2.shared.b16 {%0,%1}, [%2];"
                 : "=r"(r[0]), "=r"(r[1]) : "r"(addr));
}
__device__ __forceinline__ void mma_bf16(float* c, const uint32_t* a, const uint32_t* b) {
    asm volatile(
        "mma.sync.aligned.m16n8k16.row.col.f32.bf16.bf16.f32 "
        "{%0,%1,%2,%3}, {%4,%5,%6,%7}, {%8,%9}, {%0,%1,%2,%3};"
        : "+f"(c[0]), "+f"(c[1]), "+f"(c[2]), "+f"(c[3])
        : "r"(a[0]), "r"(a[1]), "r"(a[2]), "r"(a[3]), "r"(b[0]), "r"(b[1]));
}
__device__ __forceinline__ void split4(float4 v, uint2& hi, uint2& lo) {
    __nv_bfloat162 h01 = __floats2bfloat162_rn(v.x, v.y);
    __nv_bfloat162 h23 = __floats2bfloat162_rn(v.z, v.w);
    float r0 = v.x - __bfloat162float(h01.x);
    float r1 = v.y - __bfloat162float(h01.y);
    float r2 = v.z - __bfloat162float(h23.x);
    float r3 = v.w - __bfloat162float(h23.y);
    __nv_bfloat162 l01 = __floats2bfloat162_rn(r0, r1);
    __nv_bfloat162 l23 = __floats2bfloat162_rn(r2, r3);
    hi.x = *(uint32_t*)&h01; hi.y = *(uint32_t*)&h23;
    lo.x = *(uint32_t*)&l01; lo.y = *(uint32_t*)&l23;
}

// ---------------- small kernels ---------------------------------------------
__global__ void k_zero() {
    int i = blockIdx.x * blockDim.x + threadIdx.x;
    int stride = gridDim.x * blockDim.x;
    for (int j = i; j < C_PAD * DIN; j += stride) g_class_sum[j] = 0.f;
    for (int j = i; j < C_PAD; j += stride) g_cnt[j] = 0.f;
    for (int j = i; j < DIN; j += stride) g_total[j] = 0.f;
    if (i == 0) g_lbl_is64 = 1;
}

// split W1 once: fp32 -> bf16 hi/lo
__global__ void k_wsplit(const float* __restrict__ W1w) {
    int row = blockIdx.x;
    int t = threadIdx.x;
    float4 v = ((const float4*)(W1w + (size_t)row * DIN))[t];
    uint2 hi, lo; split4(v, hi, lo);
    *(uint2*)(g_wh + (size_t)row * DIN + 4 * t) = hi;
    *(uint2*)(g_wl + (size_t)row * DIN + 4 * t) = lo;
}

__global__ void k_detect(const int* __restrict__ lw) {
    int i = blockIdx.x * blockDim.x + threadIdx.x;
    if (i < B_ROWS / 2) {
        if (lw[2 * i + 1] != 0) g_lbl_is64 = 0;
    }
}

// segment-sum x by label: 4 rows per CTA, MLP 4
__global__ void k_scatter(const float* __restrict__ x, const void* __restrict__ lbl) {
    int t = threadIdx.x;
    int row0 = blockIdx.x * 4;
    int is64 = g_lbl_is64;
    int c[4];
    float4 v[4];
#pragma unroll
    for (int r = 0; r < 4; ++r) {
        c[r] = load_label(lbl, row0 + r, is64);
        v[r] = ((const float4*)(x + (size_t)(row0 + r) * DIN))[t];
    }
#pragma unroll
    for (int r = 0; r < 4; ++r)
        atomicAdd(((float4*)(g_class_sum + (size_t)c[r] * DIN)) + t, v[r]);
    if (t < 4) atomicAdd(&g_cnt[c[t]], 1.0f);
}

// total_sum over classes. grid (16,16)
__global__ void k_total() {
    int col  = blockIdx.x * 64 + (threadIdx.x & 63);
    int part = threadIdx.x >> 6;
    int c0 = blockIdx.y * 64 + part * 16;
    float s = 0.f;
#pragma unroll
    for (int c = c0; c < c0 + 16; ++c) s += g_class_sum[(size_t)c * DIN + col];
    __shared__ float red[256];
    red[threadIdx.x] = s;
    __syncthreads();
    if (part == 0)
        atomicAdd(&g_total[col], red[threadIdx.x] + red[threadIdx.x + 64] +
                                 red[threadIdx.x + 128] + red[threadIdx.x + 192]);
}

// M2[c] = mean_c @ W2^T + b2
__global__ __launch_bounds__(256) void k_m2(const float* __restrict__ W2w,
                                            const float* __restrict__ W2b) {
    __shared__ float As[32][33];
    __shared__ float Bs[32][68];
    __shared__ float sscale[32];

    int n0 = blockIdx.x * 64;
    int c0 = blockIdx.y * 32;
    int tid = threadIdx.x;

    if (tid < 32) {
        float cnt = g_cnt[c0 + tid];
        float oc = (float)B_ROWS - cnt;
        sscale[tid] = (oc > 0.5f) ? (1.0f / oc) : 0.0f;
    }
    __syncthreads();

    int am = tid >> 3;
    int ak = (tid & 7) * 4;
    int tx = tid & 15, ty = tid >> 4;
    float acc[2][4] = {};

    for (int k0 = 0; k0 < DIN; k0 += 32) {
        float4 t4 = *(const float4*)(g_total + k0 + ak);
        float4 s4 = *(const float4*)(g_class_sum + (size_t)(c0 + am) * DIN + k0 + ak);
        float sc = sscale[am];
        __syncthreads();
        As[ak + 0][am] = (t4.x - s4.x) * sc;
        As[ak + 1][am] = (t4.y - s4.y) * sc;
        As[ak + 2][am] = (t4.z - s4.z) * sc;
        As[ak + 3][am] = (t4.w - s4.w) * sc;
#pragma unroll
        for (int it = 0; it < 2; ++it) {
            int idx = tid + it * 256;
            int bn = idx >> 3;
            int bk = (idx & 7) * 4;
            float4 w4 = *(const float4*)(W2w + (size_t)(n0 + bn) * DIN + k0 + bk);
            Bs[bk + 0][bn] = w4.x;
            Bs[bk + 1][bn] = w4.y;
            Bs[bk + 2][bn] = w4.z;
            Bs[bk + 3][bn] = w4.w;
        }
        __syncthreads();
#pragma unroll
        for (int k = 0; k < 32; ++k) {
            float a0 = As[k][2 * ty + 0];
            float a1 = As[k][2 * ty + 1];
            float4 b = *(const float4*)(&Bs[k][4 * tx]);
            acc[0][0] += a0 * b.x; acc[0][1] += a0 * b.y;
            acc[0][2] += a0 * b.z; acc[0][3] += a0 * b.w;
            acc[1][0] += a1 * b.x; acc[1][1] += a1 * b.y;
            acc[1][2] += a1 * b.z; acc[1][3] += a1 * b.w;
        }
    }
#pragma unroll
    for (int r = 0; r < 2; ++r) {
        int c = c0 + 2 * ty + r;
        int n = n0 + 4 * tx;
        float4 bb = *(const float4*)(W2b + n);
        float4 o;
        o.x = acc[r][0] + bb.x; o.y = acc[r][1] + bb.y;
        o.z = acc[r][2] + bb.z; o.w = acc[r][3] + bb.w;
        *(float4*)(g_M2 + (size_t)c * DOUT + n) = o;
    }
}

// ---------------- k_main v5: 3-stage pipeline, B streamed as bf16 ------------
// Stage s = kc % 3 for both x-fp32 and B-bf16. Prefetch distance 2 -> the
// written stage (kc+2)%3 is never the stage being read (kc%3) or next ((kc+1)%3).
#define KC      32
#define NC      (DIN / KC)                     // 32 chunks
#define FST     36                             // fp32 stage row stride (floats)
#define XF_SZ   (128 * FST * 4)                // 18432 B per x stage
#define AST     40                             // bf16 row stride (elems) = 80 B
#define ABH_SZ  (128 * AST * 2)                // 10240 B per A half
#define BBH_SZ  (256 * AST * 2)                // 20480 B per B half
#define BST     (2 * BBH_SZ)                   // 40960 B per B stage (hi+lo)
#define BQ_OFF  (3 * XF_SZ)                    // 55296
#define A_OFF   (BQ_OFF + 3 * BST)             // 178176
#define SM_TOT  (A_OFF + 2 * ABH_SZ)           // 198656 B

__global__ __launch_bounds__(256, 1) void k_main(const float* __restrict__ x,
                                                 float* __restrict__ out) {
    extern __shared__ char sm[];
    uint32_t smb = smem_u32(sm);
    int tid = threadIdx.x;
    int wid = tid >> 5, lane = tid & 31;
    int wm = wid >> 2, wn = wid & 3;
    int m0 = blockIdx.x * 128;

    int a_r = wm * 64 + (lane & 15);
    int a_k = (lane >> 4) * 8;
    int b_r = wn * 64 + (lane & 7);
    int b_k = ((lane >> 3) & 1) * 8;

    float acc[4][8][4];
#pragma unroll
    for (int i = 0; i < 4; ++i)
#pragma unroll
        for (int j = 0; j < 8; ++j)
#pragma unroll
            for (int q = 0; q < 4; ++q) acc[i][j][q] = 0.f;

    // stage loader: x fp32 (4 cp16/thread) + B bf16 hi/lo (8 cp16/thread)
    auto load_stage = [&](int s, int k0) {
        uint32_t xbase = smb + s * XF_SZ;
#pragma unroll
        for (int i = 0; i < 4; ++i) {
            int c = tid + 256 * i;
            int row = c >> 3, kq = c & 7;
            cp16(xbase + row * (FST * 4) + kq * 16,
                 x + (size_t)(m0 + row) * DIN + k0 + 4 * kq);
        }
        uint32_t bbase = smb + BQ_OFF + s * BST;
#pragma unroll
        for (int i = 0; i < 4; ++i) {
            int c = tid + 256 * i;
            int row = c >> 2, kq = c & 3;
            cp16(bbase + row * (AST * 2) + kq * 16,
                 g_wh + (size_t)row * DIN + k0 + 8 * kq);
        }
#pragma unroll
        for (int i = 0; i < 4; ++i) {
            int c = tid + 256 * i;
            int row = c >> 2, kq = c & 3;
            cp16(bbase + BBH_SZ + row * (AST * 2) + kq * 16,
                 g_wl + (size_t)row * DIN + k0 + 8 * kq);
        }
    };

    load_stage(0, 0);       CP_COMMIT();
    load_stage(1, KC);      CP_COMMIT();

    uint32_t AH = smb + A_OFF;
    uint32_t AL = AH + ABH_SZ;

    for (int kc = 0; kc < NC; ++kc) {
        int s = kc % 3;
        CP_WAIT1();                 // chunk kc resident (only newest group pending)
        __syncthreads();            // data visible; prev iter's smem reads complete

        // convert x fp32 stage s -> AH/AL (4 float4/thread)
        uint32_t fx_off = s * XF_SZ;
#pragma unroll
        for (int i = 0; i < 4; ++i) {
            int c = tid + 256 * i;
            int row = c >> 3, kq = c & 7;
            float4 v = *(const float4*)(sm + fx_off + row * (FST * 4) + kq * 16);
            uint2 hi, lo; split4(v, hi, lo);
            uint32_t doff = row * (AST * 2) + kq * 8;
            *(uint2*)(sm + A_OFF + doff) = hi;
            *(uint2*)(sm + A_OFF + ABH_SZ + doff) = lo;
        }
        __syncthreads();            // A tiles ready

        // prefetch chunk kc+2 into stage (kc+2)%3 — disjoint from s and (kc+1)%3
        if (kc + 2 < NC) load_stage((kc + 2) % 3, (kc + 2) * KC);
        CP_COMMIT();                // commit every iter (possibly empty) -> WAIT1 exact

        uint32_t BH = smb + BQ_OFF + s * BST;
        uint32_t BL = BH + BBH_SZ;

#pragma unroll
        for (int kk = 0; kk < KC; kk += 16) {
            uint32_t ah[4][4], al[4][4];
#pragma unroll
            for (int mi = 0; mi < 4; ++mi) {
                uint32_t off = (uint32_t)((a_r + mi * 16) * AST + kk + a_k) * 2;
                ldsm_x4(AH + off, ah[mi]);
                ldsm_x4(AL + off, al[mi]);
            }
#pragma unroll
            for (int ni = 0; ni < 8; ++ni) {
                uint32_t boff = (uint32_t)((b_r + ni * 8) * AST + kk + b_k) * 2;
                uint32_t bh[2], bl[2];
                ldsm_x2(BH + boff, bh);
                ldsm_x2(BL + boff, bl);
#pragma unroll
                for (int mi = 0; mi < 4; ++mi) {
                    mma_bf16(acc[mi][ni], ah[mi], bh);
                    mma_bf16(acc[mi][ni], ah[mi], bl);
                    mma_bf16(acc[mi][ni], al[mi], bh);
                }
            }
        }
    }

    // write raw GEMM result (epilogue kernel adds b1 + M2[label])
    int nlo = (lane & 3) * 2;
    int rbase = m0 + wm * 64 + (lane >> 2);
#pragma unroll
    for (int mi = 0; mi < 4; ++mi) {
        int r0 = rbase + mi * 16;
        int r1 = r0 + 8;
        float* o0 = out + (size_t)r0 * DOUT;
        float* o1 = out + (size_t)r1 * DOUT;
#pragma unroll
        for (int ni = 0; ni < 8; ++ni) {
            int n = wn * 64 + ni * 8 + nlo;
            float2 vA, vB;
            vA.x = acc[mi][ni][0]; vA.y = acc[mi][ni][1];
            vB.x = acc[mi][ni][2]; vB.y = acc[mi][ni][3];
            *(float2*)(o0 + n) = vA;
            *(float2*)(o1 + n) = vB;
        }
    }
}

// epilogue: out[m][n] += b1[n] + M2[label[m]][n]
__global__ __launch_bounds__(256) void k_epi(const void* __restrict__ lbl,
                                             const float* __restrict__ W1b,
                                             float* __restrict__ out) {
    int t = threadIdx.x;
    int row = blockIdx.x * 4 + (t >> 6);
    int n = (t & 63) * 4;
    int is64 = g_lbl_is64;
    int c = load_label(lbl, row, is64);
    float4 bb = *(const float4*)(W1b + n);
    float4 mm = *(const float4*)(g_M2 + (size_t)c * DOUT + n);
    float4* op = (float4*)(out + (size_t)row * DOUT + n);
    float4 o = *op;
    o.x += bb.x + mm.x; o.y += bb.y + mm.y;
    o.z += bb.z + mm.z; o.w += bb.w + mm.w;
    *op = o;
}

// ---------------- launch ----------------------------------------------------
extern "C" void kernel_launch(void* const* d_in, const int* in_sizes, int n_in,
                              void* d_out, int out_size) {
    const float* x   = (const float*)d_in[0];
    const void*  lbl = d_in[1];
    const float* W1w = (const float*)d_in[2];
    const float* W1b = (const float*)d_in[3];
    const float* W2w = (const float*)d_in[4];
    const float* W2b = (const float*)d_in[5];
    float* out = (float*)d_out;

    cudaFuncSetAttribute(k_main, cudaFuncAttributeMaxDynamicSharedMemorySize, SM_TOT);

    k_zero<<<512, 256>>>();
    k_wsplit<<<DOUT, 256>>>(W1w);
    k_detect<<<32, 256>>>((const int*)lbl);
    k_main<<<128, 256, SM_TOT>>>(x, out);          // 4th launch -> ncu capture slot
    k_scatter<<<B_ROWS / 4, 256>>>(x, lbl);
    k_total<<<dim3(16, 16), 256>>>();
    k_m2<<<dim3(4, 32), 256>>>(W2w, W2b);
    k_epi<<<B_ROWS / 4, 256>>>(lbl, W1b, out);
}

// round 10
// speedup vs baseline: 1.5796x; 1.0244x over previous
#include <cuda_runtime.h>
#include <cuda_bf16.h>
#include <cstdint>

#define C_PAD   1024
#define B_ROWS  16384
#define DIN     1024
#define DOUT    256

// ---------------- scratch (static __device__, no allocation) ----------------
__device__ __align__(16) float g_class_sum[C_PAD * DIN];   // 4 MB (written by gather)
__device__ int   g_icnt[C_PAD];
__device__ float g_total[DIN];
__device__ __align__(16) float g_M2[C_PAD * DOUT];         // 1 MB
__device__ int   g_lbl_is64;
__device__ __align__(16) __nv_bfloat16 g_wh[DOUT * DIN];   // 0.5 MB
__device__ __align__(16) __nv_bfloat16 g_wl[DOUT * DIN];   // 0.5 MB
__device__ int   g_rows[C_PAD * B_ROWS];                   // 64 MB CSR row lists

// ---------------- helpers ----------------------------------------------------
__device__ __forceinline__ int load_label(const void* l, int i, int is64) {
    if (is64) return (int)(((const long long*)l)[i]);
    return ((const int*)l)[i];
}
__device__ __forceinline__ uint32_t smem_u32(const void* p) {
    uint32_t a;
    asm("{ .reg .u64 t; cvta.to.shared.u64 t, %1; cvt.u32.u64 %0, t; }" : "=r"(a) : "l"(p));
    return a;
}
__device__ __forceinline__ void cp16(uint32_t dst, const void* src) {
    asm volatile("cp.async.cg.shared.global [%0], [%1], 16;" :: "r"(dst), "l"(src));
}
#define CP_COMMIT() asm volatile("cp.async.commit_group;" ::: "memory")
#define CP_WAIT1()  asm volatile("cp.async.wait_group 1;" ::: "memory")

__device__ __forceinline__ void ldsm_x4(uint32_t addr, uint32_t* r) {
    asm volatile("ldmatrix.sync.aligned.m8n8.x4.shared.b16 {%0,%1,%2,%3}, [%4];"
                 : "=r"(r[0]), "=r"(r[1]), "=r"(r[2]), "=r"(r[3]) : "r"(addr));
}
__device__ __forceinline__ void ldsm_x2(uint32_t addr, uint32_t* r) {
    asm volatile("ldmatrix.sync.aligned.m8n8.x2.shared.b16 {%0,%1}, [%2];"
                 : "=r"(r[0]), "=r"(r[1]) : "r"(addr));
}
__device__ __forceinline__ void mma_bf16(float* c, const uint32_t* a, const uint32_t* b) {
    asm volatile(
        "mma.sync.aligned.m16n8k16.row.col.f32.bf16.bf16.f32 "
        "{%0,%1,%2,%3}, {%4,%5,%6,%7}, {%8,%9}, {%0,%1,%2,%3};"
        : "+f"(c[0]), "+f"(c[1]), "+f"(c[2]), "+f"(c[3])
        : "r"(a[0]), "r"(a[1]), "r"(a[2]), "r"(a[3]), "r"(b[0]), "r"(b[1]));
}
__device__ __forceinline__ void split4(float4 v, uint2& hi, uint2& lo) {
    __nv_bfloat162 h01 = __floats2bfloat162_rn(v.x, v.y);
    __nv_bfloat162 h23 = __floats2bfloat162_rn(v.z, v.w);
    float r0 = v.x - __bfloat162float(h01.x);
    float r1 = v.y - __bfloat162float(h01.y);
    float r2 = v.z - __bfloat162float(h23.x);
    float r3 = v.w - __bfloat162float(h23.y);
    __nv_bfloat162 l01 = __floats2bfloat162_rn(r0, r1);
    __nv_bfloat162 l23 = __floats2bfloat162_rn(r2, r3);
    hi.x = *(uint32_t*)&h01; hi.y = *(uint32_t*)&h23;
    lo.x = *(uint32_t*)&l01; lo.y = *(uint32_t*)&l23;
}

// ---------------- small kernels ---------------------------------------------
__global__ void k_zero() {
    int i = blockIdx.x * blockDim.x + threadIdx.x;
    if (i < C_PAD) g_icnt[i] = 0;
    if (i < DIN) g_total[i] = 0.f;
    if (i == 0) g_lbl_is64 = 1;
}

// split W1 once: fp32 -> bf16 hi/lo
__global__ void k_wsplit(const float* __restrict__ W1w) {
    int row = blockIdx.x;
    int t = threadIdx.x;
    float4 v = ((const float4*)(W1w + (size_t)row * DIN))[t];
    uint2 hi, lo; split4(v, hi, lo);
    *(uint2*)(g_wh + (size_t)row * DIN + 4 * t) = hi;
    *(uint2*)(g_wl + (size_t)row * DIN + 4 * t) = lo;
}

__global__ void k_detect(const int* __restrict__ lw) {
    int i = blockIdx.x * blockDim.x + threadIdx.x;
    if (i < B_ROWS / 2) {
        if (lw[2 * i + 1] != 0) g_lbl_is64 = 0;
    }
}

// CSR build: row lists per class (int atomics only)
__global__ void k_count(const void* __restrict__ lbl) {
    int i = blockIdx.x * blockDim.x + threadIdx.x;
    int is64 = g_lbl_is64;
    int c = load_label(lbl, i, is64);
    int slot = atomicAdd(&g_icnt[c], 1);
    g_rows[(size_t)c * B_ROWS + slot] = i;
}

// gather-sum: one CTA per class, register-resident column sums, no float atomics
__global__ __launch_bounds__(256) void k_gather(const float* __restrict__ x) {
    int c = blockIdx.x;
    int t = threadIdx.x;
    int n = g_icnt[c];
    const int* rows = g_rows + (size_t)c * B_ROWS;
    float4 a0 = {0.f, 0.f, 0.f, 0.f};
    float4 a1 = {0.f, 0.f, 0.f, 0.f};
    int r = 0;
    for (; r + 2 <= n; r += 2) {
        int i0 = rows[r], i1 = rows[r + 1];
        float4 v0 = ((const float4*)(x + (size_t)i0 * DIN))[t];
        float4 v1 = ((const float4*)(x + (size_t)i1 * DIN))[t];
        a0.x += v0.x; a0.y += v0.y; a0.z += v0.z; a0.w += v0.w;
        a1.x += v1.x; a1.y += v1.y; a1.z += v1.z; a1.w += v1.w;
    }
    if (r < n) {
        float4 v0 = ((const float4*)(x + (size_t)rows[r] * DIN))[t];
        a0.x += v0.x; a0.y += v0.y; a0.z += v0.z; a0.w += v0.w;
    }
    float4 o;
    o.x = a0.x + a1.x; o.y = a0.y + a1.y;
    o.z = a0.z + a1.z; o.w = a0.w + a1.w;
    ((float4*)(g_class_sum + (size_t)c * DIN))[t] = o;
}

// total_sum over classes. grid (16,16)
__global__ void k_total() {
    int col  = blockIdx.x * 64 + (threadIdx.x & 63);
    int part = threadIdx.x >> 6;
    int c0 = blockIdx.y * 64 + part * 16;
    float s = 0.f;
#pragma unroll
    for (int c = c0; c < c0 + 16; ++c) s += g_class_sum[(size_t)c * DIN + col];
    __shared__ float red[256];
    red[threadIdx.x] = s;
    __syncthreads();
    if (part == 0)
        atomicAdd(&g_total[col], red[threadIdx.x] + red[threadIdx.x + 64] +
                                 red[threadIdx.x + 128] + red[threadIdx.x + 192]);
}

// M2[c] = mean_c @ W2^T + b2
__global__ __launch_bounds__(256) void k_m2(const float* __restrict__ W2w,
                                            const float* __restrict__ W2b) {
    __shared__ float As[32][33];
    __shared__ float Bs[32][68];
    __shared__ float sscale[32];

    int n0 = blockIdx.x * 64;
    int c0 = blockIdx.y * 32;
    int tid = threadIdx.x;

    if (tid < 32) {
        float cnt = (float)g_icnt[c0 + tid];
        float oc = (float)B_ROWS - cnt;
        sscale[tid] = (oc > 0.5f) ? (1.0f / oc) : 0.0f;
    }
    __syncthreads();

    int am = tid >> 3;
    int ak = (tid & 7) * 4;
    int tx = tid & 15, ty = tid >> 4;
    float acc[2][4] = {};

    for (int k0 = 0; k0 < DIN; k0 += 32) {
        float4 t4 = *(const float4*)(g_total + k0 + ak);
        float4 s4 = *(const float4*)(g_class_sum + (size_t)(c0 + am) * DIN + k0 + ak);
        float sc = sscale[am];
        __syncthreads();
        As[ak + 0][am] = (t4.x - s4.x) * sc;
        As[ak + 1][am] = (t4.y - s4.y) * sc;
        As[ak + 2][am] = (t4.z - s4.z) * sc;
        As[ak + 3][am] = (t4.w - s4.w) * sc;
#pragma unroll
        for (int it = 0; it < 2; ++it) {
            int idx = tid + it * 256;
            int bn = idx >> 3;
            int bk = (idx & 7) * 4;
            float4 w4 = *(const float4*)(W2w + (size_t)(n0 + bn) * DIN + k0 + bk);
            Bs[bk + 0][bn] = w4.x;
            Bs[bk + 1][bn] = w4.y;
            Bs[bk + 2][bn] = w4.z;
            Bs[bk + 3][bn] = w4.w;
        }
        __syncthreads();
#pragma unroll
        for (int k = 0; k < 32; ++k) {
            float a0 = As[k][2 * ty + 0];
            float a1 = As[k][2 * ty + 1];
            float4 b = *(const float4*)(&Bs[k][4 * tx]);
            acc[0][0] += a0 * b.x; acc[0][1] += a0 * b.y;
            acc[0][2] += a0 * b.z; acc[0][3] += a0 * b.w;
            acc[1][0] += a1 * b.x; acc[1][1] += a1 * b.y;
            acc[1][2] += a1 * b.z; acc[1][3] += a1 * b.w;
        }
    }
#pragma unroll
    for (int r = 0; r < 2; ++r) {
        int c = c0 + 2 * ty + r;
        int n = n0 + 4 * tx;
        float4 bb = *(const float4*)(W2b + n);
        float4 o;
        o.x = acc[r][0] + bb.x; o.y = acc[r][1] + bb.y;
        o.z = acc[r][2] + bb.z; o.w = acc[r][3] + bb.w;
        *(float4*)(g_M2 + (size_t)c * DOUT + n) = o;
    }
}

// ---------------- k_main v6: fused convert-in-MMA pipeline -------------------
// One barrier per chunk. 3 cp.async stages (x fp32 + B bf16), 2 A-bf16 buffers.
// Iter kc: bar -> prefetch(kc+2) -> MMA(kc) [Abuf[kc&1], B kc%3]
//          -> cp.wait -> convert chunk kc+1 into Abuf[(kc&1)^1] (same-thread data).
#define KC       32
#define NC       (DIN / KC)                    // 32 chunks
#define FST      36                            // fp32 stage row stride (floats)
#define XF_SZ    (128 * FST * 4)               // 18432 B per x stage
#define AST      40                            // bf16 row stride (elems) = 80 B
#define ABH_SZ   (128 * AST * 2)               // 10240 B per A half
#define ABUF_SZ  (2 * ABH_SZ)                  // 20480 B per A buffer (hi+lo)
#define BBH_SZ   (256 * AST * 2)               // 20480 B per B half
#define BST      (2 * BBH_SZ)                  // 40960 B per B stage (hi+lo)
#define BQ_OFF   (3 * XF_SZ)                   // 55296
#define ABUF_OFF (BQ_OFF + 3 * BST)            // 178176
#define SM_TOT   (ABUF_OFF + 2 * ABUF_SZ)      // 219136 B

__global__ __launch_bounds__(256, 1) void k_main(const float* __restrict__ x,
                                                 float* __restrict__ out) {
    extern __shared__ char sm[];
    uint32_t smb = smem_u32(sm);
    int tid = threadIdx.x;
    int wid = tid >> 5, lane = tid & 31;
    int wm = wid >> 2, wn = wid & 3;
    int m0 = blockIdx.x * 128;

    int a_r = wm * 64 + (lane & 15);
    int a_k = (lane >> 4) * 8;
    int b_r = wn * 64 + (lane & 7);
    int b_k = ((lane >> 3) & 1) * 8;

    float acc[4][8][4];
#pragma unroll
    for (int i = 0; i < 4; ++i)
#pragma unroll
        for (int j = 0; j < 8; ++j)
#pragma unroll
            for (int q = 0; q < 4; ++q) acc[i][j][q] = 0.f;

    auto load_stage = [&](int s, int k0) {
        uint32_t xbase = smb + s * XF_SZ;
#pragma unroll
        for (int i = 0; i < 4; ++i) {
            int c = tid + 256 * i;
            int row = c >> 3, kq = c & 7;
            cp16(xbase + row * (FST * 4) + kq * 16,
                 x + (size_t)(m0 + row) * DIN + k0 + 4 * kq);
        }
        uint32_t bbase = smb + BQ_OFF + s * BST;
#pragma unroll
        for (int i = 0; i < 4; ++i) {
            int c = tid + 256 * i;
            int row = c >> 2, kq = c & 3;
            cp16(bbase + row * (AST * 2) + kq * 16,
                 g_wh + (size_t)row * DIN + k0 + 8 * kq);
        }
#pragma unroll
        for (int i = 0; i < 4; ++i) {
            int c = tid + 256 * i;
            int row = c >> 2, kq = c & 3;
            cp16(bbase + BBH_SZ + row * (AST * 2) + kq * 16,
                 g_wl + (size_t)row * DIN + k0 + 8 * kq);
        }
    };

    // convert x fp32 stage src_s -> A buffer dst_d (same-thread data, no bar needed)
    auto convert = [&](int src_s, int dst_d) {
        uint32_t fx_off = src_s * XF_SZ;
        uint32_t aoff = ABUF_OFF + dst_d * ABUF_SZ;
#pragma unroll
        for (int i = 0; i < 4; ++i) {
            int c = tid + 256 * i;
            int row = c >> 3, kq = c & 7;
            float4 v = *(const float4*)(sm + fx_off + row * (FST * 4) + kq * 16);
            uint2 hi, lo; split4(v, hi, lo);
            uint32_t doff = row * (AST * 2) + kq * 8;
            *(uint2*)(sm + aoff + doff) = hi;
            *(uint2*)(sm + aoff + ABH_SZ + doff) = lo;
        }
    };

    load_stage(0, 0);  CP_COMMIT();
    load_stage(1, KC); CP_COMMIT();
    CP_WAIT1();                    // chunk 0 resident (for this thread's own data)
    convert(0, 0);                 // A chunk 0 -> buffer 0

    for (int kc = 0; kc < NC; ++kc) {
        int d = kc & 1;
        __syncthreads();           // Abuf[d] + B stage kc%3 visible; all prior smem reads done

        if (kc + 2 < NC) load_stage((kc + 2) % 3, (kc + 2) * KC);
        CP_COMMIT();               // one commit per iter -> wait algebra exact

        uint32_t AH = smb + ABUF_OFF + d * ABUF_SZ;
        uint32_t AL = AH + ABH_SZ;
        uint32_t BH = smb + BQ_OFF + (kc % 3) * BST;
        uint32_t BL = BH + BBH_SZ;

#pragma unroll
        for (int kk = 0; kk < KC; kk += 16) {
            uint32_t ah[4][4], al[4][4];
#pragma unroll
            for (int mi = 0; mi < 4; ++mi) {
                uint32_t off = (uint32_t)((a_r + mi * 16) * AST + kk + a_k) * 2;
                ldsm_x4(AH + off, ah[mi]);
                ldsm_x4(AL + off, al[mi]);
            }
#pragma unroll
            for (int ni = 0; ni < 8; ++ni) {
                uint32_t boff = (uint32_t)((b_r + ni * 8) * AST + kk + b_k) * 2;
                uint32_t bh[2], bl[2];
                ldsm_x2(BH + boff, bh);
                ldsm_x2(BL + boff, bl);
#pragma unroll
                for (int mi = 0; mi < 4; ++mi) {
                    mma_bf16(acc[mi][ni], ah[mi], bh);
                    mma_bf16(acc[mi][ni], ah[mi], bl);
                    mma_bf16(acc[mi][ni], al[mi], bh);
                }
            }
        }

        if (kc + 1 < NC) {
            CP_WAIT1();            // chunk kc+1 resident
            convert((kc + 1) % 3, d ^ 1);   // overlaps tensor-pipe drain
        }
    }

    // write raw GEMM result (epilogue kernel adds b1 + M2[label])
    int nlo = (lane & 3) * 2;
    int rbase = m0 + wm * 64 + (lane >> 2);
#pragma unroll
    for (int mi = 0; mi < 4; ++mi) {
        int r0 = rbase + mi * 16;
        int r1 = r0 + 8;
        float* o0 = out + (size_t)r0 * DOUT;
        float* o1 = out + (size_t)r1 * DOUT;
#pragma unroll
        for (int ni = 0; ni < 8; ++ni) {
            int n = wn * 64 + ni * 8 + nlo;
            float2 vA, vB;
            vA.x = acc[mi][ni][0]; vA.y = acc[mi][ni][1];
            vB.x = acc[mi][ni][2]; vB.y = acc[mi][ni][3];
            *(float2*)(o0 + n) = vA;
            *(float2*)(o1 + n) = vB;
        }
    }
}

// epilogue: out[m][n] += b1[n] + M2[label[m]][n]
__global__ __launch_bounds__(256) void k_epi(const void* __restrict__ lbl,
                                             const float* __restrict__ W1b,
                                             float* __restrict__ out) {
    int t = threadIdx.x;
    int row = blockIdx.x * 4 + (t >> 6);
    int n = (t & 63) * 4;
    int is64 = g_lbl_is64;
    int c = load_label(lbl, row, is64);
    float4 bb = *(const float4*)(W1b + n);
    float4 mm = *(const float4*)(g_M2 + (size_t)c * DOUT + n);
    float4* op = (float4*)(out + (size_t)row * DOUT + n);
    float4 o = *op;
    o.x += bb.x + mm.x; o.y += bb.y + mm.y;
    o.z += bb.z + mm.z; o.w += bb.w + mm.w;
    *op = o;
}

// ---------------- launch ----------------------------------------------------
extern "C" void kernel_launch(void* const* d_in, const int* in_sizes, int n_in,
                              void* d_out, int out_size) {
    const float* x   = (const float*)d_in[0];
    const void*  lbl = d_in[1];
    const float* W1w = (const float*)d_in[2];
    const float* W1b = (const float*)d_in[3];
    const float* W2w = (const float*)d_in[4];
    const float* W2b = (const float*)d_in[5];
    float* out = (float*)d_out;

    cudaFuncSetAttribute(k_main, cudaFuncAttributeMaxDynamicSharedMemorySize, SM_TOT);

    k_zero<<<4, 256>>>();
    k_wsplit<<<DOUT, 256>>>(W1w);
    k_detect<<<32, 256>>>((const int*)lbl);
    k_main<<<128, 256, SM_TOT>>>(x, out);          // 4th launch -> ncu capture slot
    k_count<<<B_ROWS / 256, 256>>>(lbl);
    k_gather<<<C_PAD, 256>>>(x);
    k_total<<<dim3(16, 16), 256>>>();
    k_m2<<<dim3(4, 32), 256>>>(W2w, W2b);
    k_epi<<<B_ROWS / 4, 256>>>(lbl, W1b, out);
}